// round 15
// baseline (speedup 1.0000x reference)
#include <cuda_runtime.h>
#include <math.h>

// Problem constants
#define BATCH 4
#define SEQ 2048
#define NWIRES 8
#define EMBED 512
#define HEADS 8
#define DK 64
#define TOKENS (BATCH * SEQ)          // 8192
#define BH (BATCH * HEADS)            // 32

// scale folded into M: 1/sqrt(64) * log2(e)
#define QSCALE (0.125f * 1.4426950408889634f)

typedef unsigned long long u64t;

// ---- packed f32x2 helpers (sm_100+) ----
__device__ __forceinline__ u64t fma2(u64t a, u64t b, u64t c) {
    u64t d; asm("fma.rn.f32x2 %0, %1, %2, %3;" : "=l"(d) : "l"(a), "l"(b), "l"(c)); return d;
}
__device__ __forceinline__ u64t mul2(u64t a, u64t b) {
    u64t d; asm("mul.rn.f32x2 %0, %1, %2;" : "=l"(d) : "l"(a), "l"(b)); return d;
}
__device__ __forceinline__ u64t add2(u64t a, u64t b) {
    u64t d; asm("add.rn.f32x2 %0, %1, %2;" : "=l"(d) : "l"(a), "l"(b)); return d;
}
__device__ __forceinline__ u64t pack2(float lo, float hi) {
    u64t d; asm("mov.b64 %0, {%1, %2};" : "=l"(d) : "f"(lo), "f"(hi)); return d;
}
__device__ __forceinline__ float2 unpack2(u64t v) {
    float lo, hi; asm("mov.b64 {%0, %1}, %2;" : "=f"(lo), "=f"(hi) : "l"(v));
    return make_float2(lo, hi);
}

// Scratch (device globals; allocation-free rule)
__device__ float g_proj[TOKENS * 8];     // [t][n], proj = cos(x + theta)
__device__ float g_M[HEADS * 64];        // [h][n][a] = QSCALE * Wq_h^T Wk_h
__device__ float g_u[BH * SEQ * 8];      // [bh][s][a] = proj_s^T M_h
__device__ float g_C[EMBED * 64];        // [f][h*8+a] = (Wc_h @ Wv_h)[f][a]
// unnormalized partials per j-half
__device__ float g_P0[TOKENS * 64];      // [t][h*8+a]
__device__ float g_P1[TOKENS * 64];
__device__ float g_L0[TOKENS * 8];       // [t][h]
__device__ float g_L1[TOKENS * 8];

// ---------------------------------------------------------------------------
// Fused P2+P4 prep (grid 8+512 blocks, 64 threads):
//   blocks [0,8):    M_h[n][a] = QSCALE * sum_d Wq[h*64+d][n] * Wk[h*64+d][a]
//   blocks [8,520):  C[f][h*8+a] = sum_d Wc[f][h*64+d] * Wv[h*64+d][a]
// ---------------------------------------------------------------------------
__global__ void __launch_bounds__(64) prep_kernel(
    const float* __restrict__ Wq, const float* __restrict__ Wk,
    const float* __restrict__ Wv, const float* __restrict__ Wc)
{
    if (blockIdx.x < 8) {
        int h = blockIdx.x;
        int n = threadIdx.x >> 3, a = threadIdx.x & 7;
        float m = 0.f;
        #pragma unroll 8
        for (int d = 0; d < 64; d++)
            m += Wq[(h * 64 + d) * 8 + n] * Wk[(h * 64 + d) * 8 + a];
        g_M[h * 64 + threadIdx.x] = m * QSCALE;
    } else {
        int f = blockIdx.x - 8;
        int h = threadIdx.x >> 3, a = threadIdx.x & 7;
        float c = 0.f;
        #pragma unroll 8
        for (int d = 0; d < 64; d++)
            c += Wc[(size_t)f * EMBED + h * 64 + d] * Wv[(h * 64 + d) * 8 + a];
        g_C[f * 64 + threadIdx.x] = c;
    }
}

// ---------------------------------------------------------------------------
// Fused P1+P3: proj = cos(x + theta); u[bh][s][a] = sum_n proj * M_h[n][a]
// One thread = one token. grid TOKENS/256, 256 threads.
// ---------------------------------------------------------------------------
__global__ void __launch_bounds__(256) proj_u_kernel(
    const float* __restrict__ x, const float* __restrict__ theta)
{
    __shared__ float sM[512];
    const int tid = threadIdx.x;
    const int t = blockIdx.x * 256 + tid;
    const int b = t >> 11, s = t & 2047;

    sM[tid] = g_M[tid];
    sM[tid + 256] = g_M[tid + 256];
    __syncthreads();

    float pr[8];
    #pragma unroll
    for (int n = 0; n < 8; n++) pr[n] = cosf(x[t * 8 + n] + theta[n]);

    float4* pp = (float4*)(g_proj + (size_t)t * 8);
    pp[0] = make_float4(pr[0], pr[1], pr[2], pr[3]);
    pp[1] = make_float4(pr[4], pr[5], pr[6], pr[7]);

    #pragma unroll
    for (int h = 0; h < 8; h++) {
        float u[8];
        #pragma unroll
        for (int a = 0; a < 8; a++) {
            float v = 0.f;
            #pragma unroll
            for (int n = 0; n < 8; n++) v += pr[n] * sM[h * 64 + n * 8 + a];
            u[a] = v;
        }
        float4* up = (float4*)(g_u + (((size_t)(b * HEADS + h) * SEQ + s) * 8));
        up[0] = make_float4(u[0], u[1], u[2], u[3]);
        up[1] = make_float4(u[4], u[5], u[6], u[7]);
    }
}

// ---------------------------------------------------------------------------
// Attention in rank-8 space, packed f32x2 over j-pairs, IPT=2 query rows
// per thread (LDS amortized 2x, register state kept small for occupancy).
// One block: 256 query rows (tid, tid+128) of one (b,h), one j-half (1024 j).
// proj half staged TRANSPOSED in shared as [n][j]: one broadcast LDS.64
// yields (proj_j[n], proj_{j+1}[n]).
// grid (SEQ/256, BH, 2), 128 threads, 4 blocks/SM -> 16 warps/SM.
// ---------------------------------------------------------------------------
__global__ void __launch_bounds__(128, 4) attn_kernel()
{
    __shared__ __align__(16) float spf[8 * 1024];   // [n][j], 32KB

    const int tid = threadIdx.x;
    const int bh = blockIdx.y, b = bh >> 3, h = bh & 7;
    const int row0 = blockIdx.x * 256 + tid;
    const int half = blockIdx.z;

    // load u for the 2 rows, packed (u,u)
    u64t u2[2][8];
    #pragma unroll
    for (int k = 0; k < 2; k++) {
        const float* up = g_u + ((size_t)bh * SEQ + row0 + k * 128) * 8;
        #pragma unroll
        for (int n = 0; n < 8; n++) { float un = up[n]; u2[k][n] = pack2(un, un); }
    }

    // stage this half's 1024 proj rows, transposed to [n][j]
    const float* pb = g_proj + ((size_t)b * SEQ + half * 1024) * 8;
    #pragma unroll
    for (int i = 0; i < 8; i++) {
        int j = tid + i * 128;
        float4 v0 = ((const float4*)(pb + j * 8))[0];
        float4 v1 = ((const float4*)(pb + j * 8))[1];
        spf[0 * 1024 + j] = v0.x; spf[1 * 1024 + j] = v0.y;
        spf[2 * 1024 + j] = v0.z; spf[3 * 1024 + j] = v0.w;
        spf[4 * 1024 + j] = v1.x; spf[5 * 1024 + j] = v1.y;
        spf[6 * 1024 + j] = v1.z; spf[7 * 1024 + j] = v1.w;
    }
    __syncthreads();

    const u64t* sp2 = (const u64t*)spf;   // [n][512] j-pairs

    u64t acc[2][8];
    u64t l2[2];
    #pragma unroll
    for (int k = 0; k < 2; k++) {
        l2[k] = 0ull;
        #pragma unroll
        for (int n = 0; n < 8; n++) acc[k][n] = 0ull;
    }

    #pragma unroll 2
    for (int jp = 0; jp < 512; jp++) {
        u64t rA[8];
        #pragma unroll
        for (int n = 0; n < 8; n++) rA[n] = sp2[n * 512 + jp];

        #pragma unroll
        for (int k = 0; k < 2; k++) {
            u64t s = mul2(u2[k][7], rA[7]);
            s = fma2(u2[k][6], rA[6], s);
            s = fma2(u2[k][5], rA[5], s);
            s = fma2(u2[k][4], rA[4], s);
            s = fma2(u2[k][3], rA[3], s);
            s = fma2(u2[k][2], rA[2], s);
            s = fma2(u2[k][1], rA[1], s);
            s = fma2(u2[k][0], rA[0], s);
            float2 sj = unpack2(s);
            float p0 = exp2f(sj.x), p1 = exp2f(sj.y);
            u64t pp = pack2(p0, p1);
            l2[k] = add2(l2[k], pp);
            #pragma unroll
            for (int n = 0; n < 8; n++) acc[k][n] = fma2(pp, rA[n], acc[k][n]);
        }
    }

    float* Pbase = half ? g_P1 : g_P0;
    float* Lbase = half ? g_L1 : g_L0;
    #pragma unroll
    for (int k = 0; k < 2; k++) {
        float2 la = unpack2(l2[k]);
        float acs[8];
        #pragma unroll
        for (int n = 0; n < 8; n++) {
            float2 a = unpack2(acc[k][n]);
            acs[n] = a.x + a.y;
        }
        const int t = b * SEQ + row0 + k * 128;
        float* P = Pbase + ((size_t)t * 64 + h * 8);
        ((float4*)P)[0] = make_float4(acs[0], acs[1], acs[2], acs[3]);
        ((float4*)P)[1] = make_float4(acs[4], acs[5], acs[6], acs[7]);
        Lbase[t * 8 + h] = la.x + la.y;
    }
}

// ---------------------------------------------------------------------------
// Final: out[t][f] = sum_c A[t][c] * C[f][c], with
//   A[t][h*8+a] = (P0+P1)[t][h*8+a] / (L0+L1)[t][h]   folded into the A-load.
// M=8192, N=512, K=64. 128x128 tile, 8x8 microtile, 256 threads.
// ---------------------------------------------------------------------------
__global__ void __launch_bounds__(256) out_gemm_kernel(float* __restrict__ out)
{
    __shared__ float As[16][128];    // [k][m]
    __shared__ float Bs[16][128];    // [k][n]
    __shared__ float sinv[128][9];   // [m-local][h] = 1/(L0+L1)

    const int lid = threadIdx.x;
    const int tx = lid & 15, ty = lid >> 4;
    const int m0 = blockIdx.x * 128, n0 = blockIdx.y * 128;

    #pragma unroll
    for (int i = lid; i < 1024; i += 256) {
        int rr = i >> 3, hh = i & 7;
        int t = m0 + rr;
        sinv[rr][hh] = 1.0f / (g_L0[t * 8 + hh] + g_L1[t * 8 + hh]);
    }
    __syncthreads();

    float acc[8][8];
    #pragma unroll
    for (int i = 0; i < 8; i++)
        #pragma unroll
        for (int j = 0; j < 8; j++) acc[i][j] = 0.f;

    #pragma unroll 1
    for (int k0 = 0; k0 < 64; k0 += 16) {
        __syncthreads();
        #pragma unroll
        for (int i = 0; i < 8; i++) {
            int idx = lid + i * 256;        // 0..2047
            int rr = idx >> 4, kk = idx & 15;
            size_t ai = (size_t)(m0 + rr) * 64 + k0 + kk;
            As[kk][rr] = (g_P0[ai] + g_P1[ai]) * sinv[rr][(k0 + kk) >> 3];
            Bs[kk][rr] = g_C[(size_t)(n0 + rr) * 64 + k0 + kk];
        }
        __syncthreads();
        #pragma unroll
        for (int kk = 0; kk < 16; kk++) {
            float a[8], bb[8];
            #pragma unroll
            for (int i = 0; i < 4; i++) {
                a[i]      = As[kk][ty * 8 + i];
                a[i + 4]  = As[kk][ty * 8 + 4 + i];
                bb[i]     = Bs[kk][tx * 8 + i];
                bb[i + 4] = Bs[kk][tx * 8 + 4 + i];
            }
            #pragma unroll
            for (int i = 0; i < 8; i++)
                #pragma unroll
                for (int j = 0; j < 8; j++) acc[i][j] += a[i] * bb[j];
        }
    }

    #pragma unroll
    for (int i = 0; i < 8; i++) {
        float* orow = out + (size_t)(m0 + ty * 8 + i) * EMBED + n0 + tx * 8;
        #pragma unroll
        for (int j = 0; j < 8; j++) orow[j] = acc[i][j];
    }
}

// ---------------------------------------------------------------------------
extern "C" void kernel_launch(void* const* d_in, const int* in_sizes, int n_in,
                              void* d_out, int out_size)
{
    (void)in_sizes; (void)n_in; (void)out_size;
    const float* x     = (const float*)d_in[0];
    const float* theta = (const float*)d_in[1];
    const float* Wq    = (const float*)d_in[2];
    const float* Wk    = (const float*)d_in[3];
    const float* Wv    = (const float*)d_in[4];
    const float* Wc    = (const float*)d_in[5];
    float* out = (float*)d_out;

    prep_kernel<<<8 + EMBED, 64>>>(Wq, Wk, Wv, Wc);
    proj_u_kernel<<<TOKENS / 256, 256>>>(x, theta);

    dim3 ag(SEQ / 256, BH, 2);
    attn_kernel<<<ag, 128>>>();

    dim3 gg(TOKENS / 128, EMBED / 128);
    out_gemm_kernel<<<gg, 256>>>(out);
}

// round 17
// speedup vs baseline: 1.3138x; 1.3138x over previous
#include <cuda_runtime.h>
#include <math.h>

// Problem constants
#define BATCH 4
#define SEQ 2048
#define NWIRES 8
#define EMBED 512
#define HEADS 8
#define DK 64
#define TOKENS (BATCH * SEQ)          // 8192
#define BH (BATCH * HEADS)            // 32
#define NQ 4                          // j-quarters

// scale folded into M: 1/sqrt(64) * log2(e)
#define QSCALE (0.125f * 1.4426950408889634f)

typedef unsigned long long u64t;

// ---- packed f32x2 helpers (sm_100+) ----
__device__ __forceinline__ u64t fma2(u64t a, u64t b, u64t c) {
    u64t d; asm("fma.rn.f32x2 %0, %1, %2, %3;" : "=l"(d) : "l"(a), "l"(b), "l"(c)); return d;
}
__device__ __forceinline__ u64t mul2(u64t a, u64t b) {
    u64t d; asm("mul.rn.f32x2 %0, %1, %2;" : "=l"(d) : "l"(a), "l"(b)); return d;
}
__device__ __forceinline__ u64t add2(u64t a, u64t b) {
    u64t d; asm("add.rn.f32x2 %0, %1, %2;" : "=l"(d) : "l"(a), "l"(b)); return d;
}
__device__ __forceinline__ u64t pack2(float lo, float hi) {
    u64t d; asm("mov.b64 %0, {%1, %2};" : "=l"(d) : "f"(lo), "f"(hi)); return d;
}
__device__ __forceinline__ float2 unpack2(u64t v) {
    float lo, hi; asm("mov.b64 {%0, %1}, %2;" : "=f"(lo), "=f"(hi) : "l"(v));
    return make_float2(lo, hi);
}
// bare MUFU.EX2
__device__ __forceinline__ float ex2(float x) {
    float y; asm("ex2.approx.ftz.f32 %0, %1;" : "=f"(y) : "f"(x)); return y;
}

// Scratch (device globals; allocation-free rule)
__device__ float g_proj[TOKENS * 8];        // [t][n], proj = cos(x + theta)
__device__ float g_M[HEADS * 64];           // [h][n][a] = QSCALE * Wq_h^T Wk_h
__device__ float g_u[BH * SEQ * 8];         // [bh][s][a] = proj_s^T M_h
__device__ float g_C[EMBED * 64];           // [f][h*8+a] = (Wc_h @ Wv_h)[f][a]
__device__ float g_P[NQ * TOKENS * 64];     // [q][t][h*8+a] unnormalized partials
__device__ float g_L[NQ * TOKENS * 8];      // [q][t][h]
__device__ float g_A[TOKENS * 64];          // combined, normalized

// ---------------------------------------------------------------------------
// Fused prep (grid 8+512 blocks, 64 threads):
//   blocks [0,8):    M_h[n][a] = QSCALE * sum_d Wq[h*64+d][n] * Wk[h*64+d][a]
//   blocks [8,520):  C[f][h*8+a] = sum_d Wc[f][h*64+d] * Wv[h*64+d][a]
// ---------------------------------------------------------------------------
__global__ void __launch_bounds__(64) prep_kernel(
    const float* __restrict__ Wq, const float* __restrict__ Wk,
    const float* __restrict__ Wv, const float* __restrict__ Wc)
{
    if (blockIdx.x < 8) {
        int h = blockIdx.x;
        int n = threadIdx.x >> 3, a = threadIdx.x & 7;
        float m = 0.f;
        #pragma unroll 8
        for (int d = 0; d < 64; d++)
            m += Wq[(h * 64 + d) * 8 + n] * Wk[(h * 64 + d) * 8 + a];
        g_M[h * 64 + threadIdx.x] = m * QSCALE;
    } else {
        int f = blockIdx.x - 8;
        int h = threadIdx.x >> 3, a = threadIdx.x & 7;
        float c = 0.f;
        #pragma unroll 8
        for (int d = 0; d < 64; d++)
            c += Wc[(size_t)f * EMBED + h * 64 + d] * Wv[(h * 64 + d) * 8 + a];
        g_C[f * 64 + threadIdx.x] = c;
    }
}

// ---------------------------------------------------------------------------
// Fused: proj = cos(x + theta); u[bh][s][a] = sum_n proj * M_h[n][a]
// One thread = one token. grid TOKENS/256, 256 threads.
// ---------------------------------------------------------------------------
__global__ void __launch_bounds__(256) proj_u_kernel(
    const float* __restrict__ x, const float* __restrict__ theta)
{
    __shared__ float sM[512];
    const int tid = threadIdx.x;
    const int t = blockIdx.x * 256 + tid;
    const int b = t >> 11, s = t & 2047;

    sM[tid] = g_M[tid];
    sM[tid + 256] = g_M[tid + 256];
    __syncthreads();

    float pr[8];
    #pragma unroll
    for (int n = 0; n < 8; n++) pr[n] = cosf(x[t * 8 + n] + theta[n]);

    float4* pp = (float4*)(g_proj + (size_t)t * 8);
    pp[0] = make_float4(pr[0], pr[1], pr[2], pr[3]);
    pp[1] = make_float4(pr[4], pr[5], pr[6], pr[7]);

    #pragma unroll
    for (int h = 0; h < 8; h++) {
        float u[8];
        #pragma unroll
        for (int a = 0; a < 8; a++) {
            float v = 0.f;
            #pragma unroll
            for (int n = 0; n < 8; n++) v += pr[n] * sM[h * 64 + n * 8 + a];
            u[a] = v;
        }
        float4* up = (float4*)(g_u + (((size_t)(b * HEADS + h) * SEQ + s) * 8));
        up[0] = make_float4(u[0], u[1], u[2], u[3]);
        up[1] = make_float4(u[4], u[5], u[6], u[7]);
    }
}

// ---------------------------------------------------------------------------
// Attention in rank-8 space, packed f32x2 over j-pairs, IPT=2 query rows.
// One block: 256 query rows (tid, tid+128) of one (b,h), one j-QUARTER
// (512 j, 16KB smem tile transposed to [n][j]).
// grid (SEQ/256, BH, 4) = 1024 blocks, 128 threads, 4 blocks/SM.
// ---------------------------------------------------------------------------
__global__ void __launch_bounds__(128, 4) attn_kernel()
{
    __shared__ __align__(16) float spf[8 * 512];   // [n][j], 16KB

    const int tid = threadIdx.x;
    const int bh = blockIdx.y, b = bh >> 3, h = bh & 7;
    const int row0 = blockIdx.x * 256 + tid;
    const int quarter = blockIdx.z;

    // load u for the 2 rows, packed (u,u)
    u64t u2[2][8];
    #pragma unroll
    for (int k = 0; k < 2; k++) {
        const float* up = g_u + ((size_t)bh * SEQ + row0 + k * 128) * 8;
        #pragma unroll
        for (int n = 0; n < 8; n++) { float un = up[n]; u2[k][n] = pack2(un, un); }
    }

    // stage this quarter's 512 proj rows, transposed to [n][j]
    const float* pb = g_proj + ((size_t)b * SEQ + quarter * 512) * 8;
    #pragma unroll
    for (int i = 0; i < 4; i++) {
        int j = tid + i * 128;
        float4 v0 = ((const float4*)(pb + j * 8))[0];
        float4 v1 = ((const float4*)(pb + j * 8))[1];
        spf[0 * 512 + j] = v0.x; spf[1 * 512 + j] = v0.y;
        spf[2 * 512 + j] = v0.z; spf[3 * 512 + j] = v0.w;
        spf[4 * 512 + j] = v1.x; spf[5 * 512 + j] = v1.y;
        spf[6 * 512 + j] = v1.z; spf[7 * 512 + j] = v1.w;
    }
    __syncthreads();

    const u64t* sp2 = (const u64t*)spf;   // [n][256] j-pairs

    u64t acc[2][8];
    u64t l2[2];
    #pragma unroll
    for (int k = 0; k < 2; k++) {
        l2[k] = 0ull;
        #pragma unroll
        for (int n = 0; n < 8; n++) acc[k][n] = 0ull;
    }

    #pragma unroll 2
    for (int jp = 0; jp < 256; jp++) {
        u64t rA[8];
        #pragma unroll
        for (int n = 0; n < 8; n++) rA[n] = sp2[n * 256 + jp];

        #pragma unroll
        for (int k = 0; k < 2; k++) {
            u64t s = mul2(u2[k][7], rA[7]);
            s = fma2(u2[k][6], rA[6], s);
            s = fma2(u2[k][5], rA[5], s);
            s = fma2(u2[k][4], rA[4], s);
            s = fma2(u2[k][3], rA[3], s);
            s = fma2(u2[k][2], rA[2], s);
            s = fma2(u2[k][1], rA[1], s);
            s = fma2(u2[k][0], rA[0], s);
            float2 sj = unpack2(s);
            float p0 = ex2(sj.x), p1 = ex2(sj.y);
            u64t pp = pack2(p0, p1);
            l2[k] = add2(l2[k], pp);
            #pragma unroll
            for (int n = 0; n < 8; n++) acc[k][n] = fma2(pp, rA[n], acc[k][n]);
        }
    }

    float* Pbase = g_P + (size_t)quarter * TOKENS * 64;
    float* Lbase = g_L + (size_t)quarter * TOKENS * 8;
    #pragma unroll
    for (int k = 0; k < 2; k++) {
        float2 la = unpack2(l2[k]);
        float acs[8];
        #pragma unroll
        for (int n = 0; n < 8; n++) {
            float2 a = unpack2(acc[k][n]);
            acs[n] = a.x + a.y;
        }
        const int t = b * SEQ + row0 + k * 128;
        float* P = Pbase + ((size_t)t * 64 + h * 8);
        ((float4*)P)[0] = make_float4(acs[0], acs[1], acs[2], acs[3]);
        ((float4*)P)[1] = make_float4(acs[4], acs[5], acs[6], acs[7]);
        Lbase[t * 8 + h] = la.x + la.y;
    }
}

// ---------------------------------------------------------------------------
// Combine quarters and normalize: g_A[t][c] = sum_q P[q][t][c] / sum_q L[q][t][h]
// grid TOKENS*64/256, 256 threads.
// ---------------------------------------------------------------------------
__global__ void __launch_bounds__(256) combine_kernel()
{
    int idx = blockIdx.x * 256 + threadIdx.x;   // t*64 + c
    int t = idx >> 6, c = idx & 63, h = c >> 3;

    float p = g_P[idx] + g_P[TOKENS * 64 + idx]
            + g_P[2 * TOKENS * 64 + idx] + g_P[3 * TOKENS * 64 + idx];
    int li = t * 8 + h;
    float l = g_L[li] + g_L[TOKENS * 8 + li]
            + g_L[2 * TOKENS * 8 + li] + g_L[3 * TOKENS * 8 + li];
    g_A[idx] = p / l;
}

// ---------------------------------------------------------------------------
// Final: out[t][f] = sum_c A[t][c] * C[f][c].  M=8192, N=512, K=64.
// 128x64 tile, 8x4 microtile, 256 threads, grid (64, 8) = 512 blocks.
// ---------------------------------------------------------------------------
__global__ void __launch_bounds__(256) out_gemm_kernel(float* __restrict__ out)
{
    __shared__ float As[16][128];    // [k][m]
    __shared__ float Bs[16][64];     // [k][n]

    const int lid = threadIdx.x;
    const int tx = lid & 15, ty = lid >> 4;
    const int m0 = blockIdx.x * 128, n0 = blockIdx.y * 64;

    float acc[8][4];
    #pragma unroll
    for (int i = 0; i < 8; i++)
        #pragma unroll
        for (int j = 0; j < 4; j++) acc[i][j] = 0.f;

    #pragma unroll 1
    for (int k0 = 0; k0 < 64; k0 += 16) {
        #pragma unroll
        for (int i = 0; i < 8; i++) {
            int idx = lid + i * 256;        // 0..2047
            int rr = idx >> 4, kk = idx & 15;
            As[kk][rr] = g_A[(size_t)(m0 + rr) * 64 + k0 + kk];
        }
        #pragma unroll
        for (int i = 0; i < 4; i++) {
            int idx = lid + i * 256;        // 0..1023
            int rr = idx >> 4, kk = idx & 15;
            Bs[kk][rr] = g_C[(size_t)(n0 + rr) * 64 + k0 + kk];
        }
        __syncthreads();
        #pragma unroll
        for (int kk = 0; kk < 16; kk++) {
            float a[8], bb[4];
            #pragma unroll
            for (int i = 0; i < 8; i++) a[i] = As[kk][ty * 8 + i];
            #pragma unroll
            for (int j = 0; j < 4; j++) bb[j] = Bs[kk][tx * 4 + j];
            #pragma unroll
            for (int i = 0; i < 8; i++)
                #pragma unroll
                for (int j = 0; j < 4; j++) acc[i][j] += a[i] * bb[j];
        }
        __syncthreads();
    }

    #pragma unroll
    for (int i = 0; i < 8; i++) {
        float4 r = make_float4(acc[i][0], acc[i][1], acc[i][2], acc[i][3]);
        *(float4*)(out + (size_t)(m0 + ty * 8 + i) * EMBED + n0 + tx * 4) = r;
    }
}

// ---------------------------------------------------------------------------
extern "C" void kernel_launch(void* const* d_in, const int* in_sizes, int n_in,
                              void* d_out, int out_size)
{
    (void)in_sizes; (void)n_in; (void)out_size;
    const float* x     = (const float*)d_in[0];
    const float* theta = (const float*)d_in[1];
    const float* Wq    = (const float*)d_in[2];
    const float* Wk    = (const float*)d_in[3];
    const float* Wv    = (const float*)d_in[4];
    const float* Wc    = (const float*)d_in[5];
    float* out = (float*)d_out;

    prep_kernel<<<8 + EMBED, 64>>>(Wq, Wk, Wv, Wc);
    proj_u_kernel<<<TOKENS / 256, 256>>>(x, theta);

    dim3 ag(SEQ / 256, BH, NQ);
    attn_kernel<<<ag, 128>>>();

    combine_kernel<<<TOKENS * 64 / 256, 256>>>();

    dim3 gg(TOKENS / 128, EMBED / 64);
    out_gemm_kernel<<<gg, 256>>>(out);
}